// round 3
// baseline (speedup 1.0000x reference)
#include <cuda_runtime.h>

#define NS   64
#define PP   4096
#define BBAT 8
#define HH   32
#define EE   34
#define NTOK (BBAT*PP)        /* 32768 rows per step */
#define NHID (NTOK*HH)        /* 1048576 floats per step */
#define QSTR 36               /* padded stride for q rows (16B aligned) */
#define KVSTR 72              /* padded stride for k+v per token */

// Scratch: q / (k,v) per token, 10 slots for the batched obs phase.
__device__ __align__(16) float g_Q [10*NTOK*QSTR];
__device__ __align__(16) float g_KV[10*NTOK*KVSTR];

// ---------------------------------------------------------------------------
// Kernel A: per-token QKV projection, 4 lanes per token.
// Lane j owns output channels i = j + 4k (k < 26), i < 102.
// token vec = [h(32), row/64, col/64]; outputs q(34) -> g_Q, k,v(34+34) -> g_KV.
// ---------------------------------------------------------------------------
__global__ void __launch_bounds__(256)
qkv_kernel(const float* __restrict__ h,
           const float* __restrict__ ipw, const float* __restrict__ ipb)
{
    __shared__ __align__(16) float sw[102*36];
    __shared__ float sb[102];
    int tid = threadIdx.x;
    for (int i = tid; i < 102*36; i += 256) {
        int ri = i / 36, ci = i - ri*36;
        sw[i] = (ci < 34) ? ipw[ri*34 + ci] : 0.f;
    }
    if (tid < 102) sb[tid] = ipb[tid];
    __syncthreads();

    int gt   = blockIdx.x * 256 + tid;
    int tok  = gt >> 2;
    int lane4 = gt & 3;
    int t = tok >> 15;             // step slot
    int n = tok & (NTOK - 1);
    int p = n & (PP - 1);

    const float4* hr4 = (const float4*)(h + (size_t)t*NHID + (size_t)n*HH);
    float xv[EE];
#pragma unroll
    for (int e4 = 0; e4 < 8; e4++) {
        float4 v = hr4[e4];       // same addr across the 4-lane group -> broadcast
        xv[e4*4+0] = v.x; xv[e4*4+1] = v.y; xv[e4*4+2] = v.z; xv[e4*4+3] = v.w;
    }
    int r = p >> 6, c = p & 63;
    xv[32] = (float)r * (1.0f/64.0f);
    xv[33] = (float)c * (1.0f/64.0f);

    float* q  = g_Q  + (size_t)tok*QSTR;
    float* kv = g_KV + (size_t)tok*KVSTR;

#pragma unroll
    for (int k = 0; k < 26; k++) {
        int i = lane4 + 4*k;
        if (i < 102) {
            float a = sb[i];
            const float* wrow = sw + i*36;
#pragma unroll
            for (int e = 0; e < EE; e++) a = fmaf(wrow[e], xv[e], a);
            if      (i < 34) q[i]         = a;
            else if (i < 68) kv[i-34]     = a;
            else             kv[36+i-68]  = a;
        }
    }
}

// ---------------------------------------------------------------------------
// Kernel B: per-center fused attention epilogue, 4 lanes per row.
// scores by neighbor ownership -> shfl gather -> softmax (replicated)
// -> av partial-by-neighbor + butterfly -> out_proj by i-ownership
// -> fc_sa partial-by-e + butterfly -> fc2 by i-ownership
// -> layernorm stats via butterfly -> strided output writes.
// smem floats: opw@0(34x36,pad0) opb@1224 saw@1260(32x36,pad0) sab@2412
//              f2w@2444(32x32) f2b@3468 lng@3500 lnb@3532
// ---------------------------------------------------------------------------
__global__ void __launch_bounds__(256)
attn_kernel(const float* __restrict__ h,
            const float* __restrict__ opw, const float* __restrict__ opb,
            const float* __restrict__ saw, const float* __restrict__ sab,
            const float* __restrict__ f2w, const float* __restrict__ f2b,
            const float* __restrict__ lng, const float* __restrict__ lnb,
            float* __restrict__ outp)
{
    __shared__ __align__(16) float sm[3564];
    int tid = threadIdx.x;
    for (int i = tid; i < 34*36; i += 256) {
        int ri = i / 36, ci = i - ri*36;
        sm[i] = (ci < 34) ? opw[ri*34 + ci] : 0.f;
    }
    for (int i = tid; i < 32*36; i += 256) {
        int ri = i / 36, ci = i - ri*36;
        sm[1260 + i] = (ci < 34) ? saw[ri*34 + ci] : 0.f;
    }
    for (int i = tid; i < 1024; i += 256) sm[2444+i] = f2w[i];
    if (tid < 34) sm[1224+tid] = opb[tid];
    if (tid < 32) sm[2412+tid] = sab[tid];
    if (tid < 32) sm[3468+tid] = f2b[tid];
    if (tid < 32) sm[3500+tid] = lng[tid];
    if (tid < 32) sm[3532+tid] = lnb[tid];
    __syncthreads();

    int gt = blockIdx.x * 256 + tid;
    int g  = gt >> 2;               // row id
    int lane4 = gt & 3;
    int t = g >> 15;
    int n = g & (NTOK - 1);
    int p = n & (PP - 1);
    int b = n >> 12;
    int r = p >> 6, c = p & 63;
    int rr = r + (r == 0) - (r == 63);   // boundary shift (not clamp)
    int cc = c + (c == 0) - (c == 63);
    int base = t*NTOK + b*PP;

    // full q of shifted center (broadcast loads within group)
    const float4* qp4 = (const float4*)(g_Q + (size_t)(base + rr*NS + cc)*QSTR);
    float q[36];
#pragma unroll
    for (int e4 = 0; e4 < 9; e4++) {
        float4 v = qp4[e4];
        q[e4*4+0] = v.x; q[e4*4+1] = v.y; q[e4*4+2] = v.z; q[e4*4+3] = v.w;
    }

    // scores: lane owns neighbors j = lane4 + 4*jj
    float sloc[3];
#pragma unroll
    for (int jj = 0; jj < 3; jj++) {
        int j = lane4 + 4*jj;
        float a = 0.f;
        if (j < 9) {
            int dy = j / 3, dx = j - dy*3;
            int np = (rr + dy - 1)*NS + (cc + dx - 1);
            const float4* kp4 = (const float4*)(g_KV + (size_t)(base + np)*KVSTR);
#pragma unroll
            for (int e4 = 0; e4 < 9; e4++) {
                float4 kvv = kp4[e4];
                if (e4 < 8) {
                    a = fmaf(q[e4*4+0], kvv.x, a);
                    a = fmaf(q[e4*4+1], kvv.y, a);
                    a = fmaf(q[e4*4+2], kvv.z, a);
                    a = fmaf(q[e4*4+3], kvv.w, a);
                } else {
                    a = fmaf(q[32], kvv.x, a);
                    a = fmaf(q[33], kvv.y, a);
                }
            }
        }
        sloc[jj] = a * 0.17149858514250882f;   // 1/sqrt(34)
    }

    // gather all 9 scores into every lane
    float s[9];
#pragma unroll
    for (int j = 0; j < 9; j++)
        s[j] = __shfl_sync(0xffffffffu, sloc[j >> 2], j & 3, 4);

    // softmax (replicated)
    float mx = s[0];
#pragma unroll
    for (int i = 1; i < 9; i++) mx = fmaxf(mx, s[i]);
    float sum = 0.f;
#pragma unroll
    for (int i = 0; i < 9; i++) { s[i] = __expf(s[i] - mx); sum += s[i]; }
    float inv = __fdividef(1.0f, sum);

    // av: partial by owned neighbors, then butterfly over the 4-lane group
    float av[EE];
#pragma unroll
    for (int e = 0; e < EE; e++) av[e] = 0.f;
#pragma unroll
    for (int jj = 0; jj < 3; jj++) {
        int j = lane4 + 4*jj;
        if (j < 9) {
            int dy = j / 3, dx = j - dy*3;
            int np = (rr + dy - 1)*NS + (cc + dx - 1);
            const float4* vp4 = (const float4*)(g_KV + (size_t)(base + np)*KVSTR + 36);
            float w = s[j] * inv;
#pragma unroll
            for (int e4 = 0; e4 < 9; e4++) {
                float4 vv = vp4[e4];
                if (e4 < 8) {
                    av[e4*4+0] = fmaf(w, vv.x, av[e4*4+0]);
                    av[e4*4+1] = fmaf(w, vv.y, av[e4*4+1]);
                    av[e4*4+2] = fmaf(w, vv.z, av[e4*4+2]);
                    av[e4*4+3] = fmaf(w, vv.w, av[e4*4+3]);
                } else {
                    av[32] = fmaf(w, vv.x, av[32]);
                    av[33] = fmaf(w, vv.y, av[33]);
                }
            }
        }
    }
#pragma unroll
    for (int e = 0; e < EE; e++) {
        av[e] += __shfl_xor_sync(0xffffffffu, av[e], 1);
        av[e] += __shfl_xor_sync(0xffffffffu, av[e], 2);
    }

    // out_proj: lane owns i = lane4 + 4k  (full av available)
    float o_own[9];
#pragma unroll
    for (int k = 0; k < 9; k++) {
        int i = lane4 + 4*k;
        float a = 0.f;
        if (i < 34) {
            a = sm[1224+i];
            const float* wrow = sm + i*36;
#pragma unroll
            for (int e = 0; e < EE; e++) a = fmaf(wrow[e], av[e], a);
        }
        o_own[k] = a;   // 0 for invalid slots; saw pad cols are zeroed
    }

    // fc_sa: partial sums over owned e = lane4+4k, butterfly to full nh
    float nh[HH];
#pragma unroll
    for (int i = 0; i < HH; i++) {
        float a = 0.f;
#pragma unroll
        for (int k = 0; k < 9; k++)
            a = fmaf(sm[1260 + i*36 + (lane4 + 4*k)], o_own[k], a);
        nh[i] = a;
    }
#pragma unroll
    for (int i = 0; i < HH; i++) {
        nh[i] += __shfl_xor_sync(0xffffffffu, nh[i], 1);
        nh[i] += __shfl_xor_sync(0xffffffffu, nh[i], 2);
    }
    // add bias + residual (replicated; broadcast loads)
    const float4* hr4 = (const float4*)(h + (size_t)t*NHID + (size_t)n*HH);
#pragma unroll
    for (int e4 = 0; e4 < 8; e4++) {
        float4 v = hr4[e4];
        nh[e4*4+0] += v.x + sm[2412+e4*4+0];
        nh[e4*4+1] += v.y + sm[2412+e4*4+1];
        nh[e4*4+2] += v.z + sm[2412+e4*4+2];
        nh[e4*4+3] += v.w + sm[2412+e4*4+3];
    }

    // fc2: lane owns i = lane4 + 4k, k < 8 (full nh available)
    float y_own[8];
    float psum = 0.f;
#pragma unroll
    for (int k = 0; k < 8; k++) {
        int i = lane4 + 4*k;
        float a = sm[3468+i];
        const float* wrow = sm + 2444 + i*32;
#pragma unroll
        for (int j = 0; j < HH; j++) a = fmaf(wrow[j], nh[j], a);
        y_own[k] = a;
        psum += a;
    }
    // layernorm stats across the group (lanes partition the 32 channels)
    psum += __shfl_xor_sync(0xffffffffu, psum, 1);
    psum += __shfl_xor_sync(0xffffffffu, psum, 2);
    float mean = psum * (1.0f/32.0f);
    float pvar = 0.f;
#pragma unroll
    for (int k = 0; k < 8; k++) { float d = y_own[k] - mean; pvar = fmaf(d, d, pvar); }
    pvar += __shfl_xor_sync(0xffffffffu, pvar, 1);
    pvar += __shfl_xor_sync(0xffffffffu, pvar, 2);
    float rinv = rsqrtf(pvar * (1.0f/32.0f) + 1e-5f);

    float* orow = outp + (size_t)g*HH;
#pragma unroll
    for (int k = 0; k < 8; k++) {
        int i = lane4 + 4*k;
        orow[i] = (y_own[k] - mean)*rinv*sm[3500+i] + sm[3532+i];
    }
}

// ---------------------------------------------------------------------------
extern "C" void kernel_launch(void* const* d_in, const int* in_sizes, int n_in,
                              void* d_out, int out_size)
{
    const float* x   = (const float*)d_in[0];
    const float* ipw = (const float*)d_in[1];
    const float* ipb = (const float*)d_in[2];
    const float* opw = (const float*)d_in[3];
    const float* opb = (const float*)d_in[4];
    const float* saw = (const float*)d_in[5];
    const float* sab = (const float*)d_in[6];
    const float* f2w = (const float*)d_in[7];
    const float* f2b = (const float*)d_in[8];
    const float* lng = (const float*)d_in[9];
    const float* lnb = (const float*)d_in[10];
    float* out = (float*)d_out;

    // Observation phase: 10 independent steps, batched.
    qkv_kernel <<<(10*NTOK*4)/256, 256>>>(x, ipw, ipb);
    attn_kernel<<<(10*NTOK*4)/256, 256>>>(x, opw, opb, saw, sab, f2w, f2b,
                                          lng, lnb, out);

    // Prediction phase: 50 sequential steps rolling on the previous output.
    for (int s = 0; s < 50; s++) {
        const float* hin = out + (size_t)(9 + s)*NHID;
        float* outstep   = out + (size_t)(10 + s)*NHID;
        qkv_kernel <<<(NTOK*4)/256, 256>>>(hin, ipw, ipb);
        attn_kernel<<<(NTOK*4)/256, 256>>>(hin, opw, opb, saw, sab, f2w, f2b,
                                           lng, lnb, outstep);
    }
}

// round 7
// speedup vs baseline: 1.9180x; 1.9180x over previous
#include <cuda_runtime.h>

#define NS   64
#define PP   4096
#define BBAT 8
#define HH   32
#define EE   34
#define NTOK (BBAT*PP)        /* 32768 rows per step */
#define NHID (NTOK*HH)        /* 1048576 floats per step */
#define QSTR 36               /* padded stride for q rows (16B aligned) */
#define KVSTR 72              /* padded stride for k+v per token */

// Scratch: q / (k,v) per token, 10 slots for the batched obs phase.
__device__ __align__(16) float g_Q [10*NTOK*QSTR];
__device__ __align__(16) float g_KV[10*NTOK*KVSTR];
// Folded epilogue weights: W2 = f2w@saw@opw (32x34, stride 36), b2 (32).
__device__ __align__(16) float g_W2[32*36];
__device__ float g_b2[32];

// ---------------------------------------------------------------------------
// Fold kernel (runs once per launch, 1 CTA): W2 = f2w @ (saw @ opw),
// b2 = f2w @ (saw @ opb + sab) + f2b.
// ---------------------------------------------------------------------------
__global__ void fold_kernel(const float* __restrict__ opw, const float* __restrict__ opb,
                            const float* __restrict__ saw, const float* __restrict__ sab,
                            const float* __restrict__ f2w, const float* __restrict__ f2b)
{
    __shared__ float sW1[32*34];
    int tid = threadIdx.x;
    for (int idx = tid; idx < 32*34; idx += 256) {
        int j = idx / 34, e = idx - j*34;
        float a = 0.f;
        for (int k = 0; k < 34; k++) a = fmaf(saw[j*34+k], opw[k*34+e], a);
        sW1[idx] = a;
    }
    __syncthreads();
    for (int idx = tid; idx < 32*34; idx += 256) {
        int i = idx / 34, e = idx - i*34;
        float a = 0.f;
        for (int j = 0; j < 32; j++) a = fmaf(f2w[i*32+j], sW1[j*34+e], a);
        g_W2[i*36+e] = a;
    }
    if (tid < 32) {
        int i = tid;
        float a = f2b[i];
        for (int j = 0; j < 32; j++) {
            float b1 = sab[j];
            for (int k = 0; k < 34; k++) b1 = fmaf(saw[j*34+k], opb[k], b1);
            a = fmaf(f2w[i*32+j], b1, a);
        }
        g_b2[i] = a;
    }
}

// ---------------------------------------------------------------------------
// Kernel A: per-token QKV projection.
// 4-wide channel blocks (4 independent FMA chains) + float4 stores.
// ---------------------------------------------------------------------------
__global__ void __launch_bounds__(256)
qkv_kernel(const float* __restrict__ h,
           const float* __restrict__ ipw, const float* __restrict__ ipb)
{
    __shared__ __align__(16) float sw[102*36];
    __shared__ float sb[102];
    int tid = threadIdx.x;
    for (int i = tid; i < 102*34; i += 256) {
        int ri = i / 34, ci = i - ri*34;
        sw[ri*36 + ci] = ipw[i];
    }
    if (tid < 102) sb[tid] = ipb[tid];
    __syncthreads();

    int tok = blockIdx.x * 256 + tid;
    int t = tok >> 15;
    int n = tok & (NTOK - 1);
    int p = n & (PP - 1);

    const float4* hr4 = (const float4*)(h + (size_t)t*NHID + (size_t)n*HH);
    float xv[EE];
#pragma unroll
    for (int e4 = 0; e4 < 8; e4++) {
        float4 v = hr4[e4];
        xv[e4*4+0] = v.x; xv[e4*4+1] = v.y; xv[e4*4+2] = v.z; xv[e4*4+3] = v.w;
    }
    int r = p >> 6, c = p & 63;
    xv[32] = (float)r * (1.0f/64.0f);
    xv[33] = (float)c * (1.0f/64.0f);

    float* q  = g_Q  + (size_t)tok*QSTR;
    float* kv = g_KV + (size_t)tok*KVSTR;
    float* dst0 = q;
    float* dst1 = kv;
    float* dst2 = kv + 36;

#pragma unroll
    for (int grp = 0; grp < 3; grp++) {
        int bc = grp * 34;
        float* d = (grp == 0) ? dst0 : (grp == 1) ? dst1 : dst2;
#pragma unroll
        for (int i0 = 0; i0 < 32; i0 += 4) {
            float a0 = sb[bc+i0+0], a1 = sb[bc+i0+1];
            float a2 = sb[bc+i0+2], a3 = sb[bc+i0+3];
            const float* w0 = sw + (bc+i0)*36;
            const float* w1 = w0 + 36;
            const float* w2 = w0 + 72;
            const float* w3 = w0 + 108;
#pragma unroll
            for (int e = 0; e < EE; e++) {
                float x = xv[e];
                a0 = fmaf(w0[e], x, a0);
                a1 = fmaf(w1[e], x, a1);
                a2 = fmaf(w2[e], x, a2);
                a3 = fmaf(w3[e], x, a3);
            }
            *(float4*)(d + i0) = make_float4(a0, a1, a2, a3);
        }
        {   // channels 32,33 of this group
            float a0 = sb[bc+32], a1 = sb[bc+33];
            const float* w0 = sw + (bc+32)*36;
            const float* w1 = w0 + 36;
#pragma unroll
            for (int e = 0; e < EE; e++) {
                float x = xv[e];
                a0 = fmaf(w0[e], x, a0);
                a1 = fmaf(w1[e], x, a1);
            }
            d[32] = a0; d[33] = a1;
        }
    }
}

// ---------------------------------------------------------------------------
// Kernel B: fused attention epilogue with folded weights.
// scores (9 interleaved accumulators) -> softmax -> av (interleaved)
// -> y = b2 + W2@av + f2w@h -> layernorm -> out.
// smem floats: W2@0 (32x36), b2@1152, f2w@1184 (32x32), lng@2208, lnb@2240
// ---------------------------------------------------------------------------
__global__ void __launch_bounds__(256)
attn_kernel(const float* __restrict__ h,
            const float* __restrict__ f2w,
            const float* __restrict__ lng, const float* __restrict__ lnb,
            float* __restrict__ outp)
{
    __shared__ __align__(16) float sm[2272];
    int tid = threadIdx.x;
    for (int i = tid; i < 32*36; i += 256) sm[i] = g_W2[i];
    for (int i = tid; i < 1024;  i += 256) sm[1184+i] = f2w[i];
    if (tid < 32) sm[1152+tid] = g_b2[tid];
    if (tid < 32) sm[2208+tid] = lng[tid];
    if (tid < 32) sm[2240+tid] = lnb[tid];
    __syncthreads();

    int g = blockIdx.x * 256 + tid;
    int t = g >> 15;
    int n = g & (NTOK - 1);
    int p = n & (PP - 1);
    int b = n >> 12;
    int r = p >> 6, c = p & 63;
    int rr = r + (r == 0) - (r == 63);   // boundary shift (not clamp)
    int cc = c + (c == 0) - (c == 63);
    int base = t*NTOK + b*PP;

    // prefetch residual/h row early
    const float4* hr4 = (const float4*)(h + (size_t)t*NHID + (size_t)n*HH);
    float hh[HH];
#pragma unroll
    for (int e4 = 0; e4 < 8; e4++) {
        float4 v = hr4[e4];
        hh[e4*4+0] = v.x; hh[e4*4+1] = v.y; hh[e4*4+2] = v.z; hh[e4*4+3] = v.w;
    }

    // q of shifted center
    const float4* qp4 = (const float4*)(g_Q + (size_t)(base + rr*NS + cc)*QSTR);
    float q[36];
#pragma unroll
    for (int e4 = 0; e4 < 9; e4++) {
        float4 v = qp4[e4];
        q[e4*4+0] = v.x; q[e4*4+1] = v.y; q[e4*4+2] = v.z; q[e4*4+3] = v.w;
    }

    // neighbor row pointers
    const float4* kp[9];
#pragma unroll
    for (int j = 0; j < 9; j++) {
        int dy = j / 3, dx = j - dy*3;
        int np = (rr + dy - 1)*NS + (cc + dx - 1);
        kp[j] = (const float4*)(g_KV + (size_t)(base + np)*KVSTR);
    }

    // scores: 9 independent accumulators, loads interleaved per e4-step
    float acc[9];
#pragma unroll
    for (int j = 0; j < 9; j++) acc[j] = 0.f;
#pragma unroll
    for (int e4 = 0; e4 < 9; e4++) {
#pragma unroll
        for (int j = 0; j < 9; j++) {
            float4 kvv = kp[j][e4];
            if (e4 < 8) {
                acc[j] = fmaf(q[e4*4+0], kvv.x, acc[j]);
                acc[j] = fmaf(q[e4*4+1], kvv.y, acc[j]);
                acc[j] = fmaf(q[e4*4+2], kvv.z, acc[j]);
                acc[j] = fmaf(q[e4*4+3], kvv.w, acc[j]);
            } else {
                acc[j] = fmaf(q[32], kvv.x, acc[j]);
                acc[j] = fmaf(q[33], kvv.y, acc[j]);
            }
        }
    }

    // softmax over 9 scores
#pragma unroll
    for (int j = 0; j < 9; j++) acc[j] *= 0.17149858514250882f;  // 1/sqrt(34)
    float mx = acc[0];
#pragma unroll
    for (int j = 1; j < 9; j++) mx = fmaxf(mx, acc[j]);
    float sum = 0.f;
#pragma unroll
    for (int j = 0; j < 9; j++) { acc[j] = __expf(acc[j] - mx); sum += acc[j]; }
    float inv = __fdividef(1.0f, sum);
#pragma unroll
    for (int j = 0; j < 9; j++) acc[j] *= inv;

    // av: accumulate across neighbors per e4-step (9 loads in flight)
    float av[EE];
#pragma unroll
    for (int e = 0; e < EE; e++) av[e] = 0.f;
#pragma unroll
    for (int e4 = 0; e4 < 9; e4++) {
#pragma unroll
        for (int j = 0; j < 9; j++) {
            float4 vv = kp[j][9 + e4];         // v half of the row
            if (e4 < 8) {
                av[e4*4+0] = fmaf(acc[j], vv.x, av[e4*4+0]);
                av[e4*4+1] = fmaf(acc[j], vv.y, av[e4*4+1]);
                av[e4*4+2] = fmaf(acc[j], vv.z, av[e4*4+2]);
                av[e4*4+3] = fmaf(acc[j], vv.w, av[e4*4+3]);
            } else {
                av[32] = fmaf(acc[j], vv.x, av[32]);
                av[33] = fmaf(acc[j], vv.y, av[33]);
            }
        }
    }

    // y = b2 + W2@av + f2w@h   (folded out_proj+fc_sa+fc2)
    float y[HH];
    float mean = 0.f;
#pragma unroll 4
    for (int i = 0; i < HH; i++) {
        float a = sm[1152+i];
        const float* wrow = sm + i*36;
#pragma unroll
        for (int e = 0; e < EE; e++) a = fmaf(wrow[e], av[e], a);
        const float* frow = sm + 1184 + i*32;
#pragma unroll
        for (int j = 0; j < HH; j++) a = fmaf(frow[j], hh[j], a);
        y[i] = a; mean += a;
    }
    mean *= (1.0f/32.0f);
    float var = 0.f;
#pragma unroll
    for (int i = 0; i < HH; i++) { float d = y[i] - mean; var = fmaf(d, d, var); }
    var *= (1.0f/32.0f);
    float rinv = rsqrtf(var + 1e-5f);

    float4* orow4 = (float4*)(outp + (size_t)g*HH);
#pragma unroll
    for (int i4 = 0; i4 < 8; i4++) {
        float4 v;
        v.x = (y[i4*4+0] - mean)*rinv*sm[2208+i4*4+0] + sm[2240+i4*4+0];
        v.y = (y[i4*4+1] - mean)*rinv*sm[2208+i4*4+1] + sm[2240+i4*4+1];
        v.z = (y[i4*4+2] - mean)*rinv*sm[2208+i4*4+2] + sm[2240+i4*4+2];
        v.w = (y[i4*4+3] - mean)*rinv*sm[2208+i4*4+3] + sm[2240+i4*4+3];
        orow4[i4] = v;
    }
}

// ---------------------------------------------------------------------------
extern "C" void kernel_launch(void* const* d_in, const int* in_sizes, int n_in,
                              void* d_out, int out_size)
{
    const float* x   = (const float*)d_in[0];
    const float* ipw = (const float*)d_in[1];
    const float* ipb = (const float*)d_in[2];
    const float* opw = (const float*)d_in[3];
    const float* opb = (const float*)d_in[4];
    const float* saw = (const float*)d_in[5];
    const float* sab = (const float*)d_in[6];
    const float* f2w = (const float*)d_in[7];
    const float* f2b = (const float*)d_in[8];
    const float* lng = (const float*)d_in[9];
    const float* lnb = (const float*)d_in[10];
    float* out = (float*)d_out;

    // Fold the three linear epilogue layers once.
    fold_kernel<<<1, 256>>>(opw, opb, saw, sab, f2w, f2b);

    // Observation phase: 10 independent steps, batched.
    qkv_kernel <<<(10*NTOK)/256, 256>>>(x, ipw, ipb);
    attn_kernel<<<(10*NTOK)/256, 256>>>(x, f2w, lng, lnb, out);

    // Prediction phase: 50 sequential steps rolling on the previous output.
    for (int s = 0; s < 50; s++) {
        const float* hin = out + (size_t)(9 + s)*NHID;
        float* outstep   = out + (size_t)(10 + s)*NHID;
        qkv_kernel <<<NTOK/256, 256>>>(hin, ipw, ipb);
        attn_kernel<<<NTOK/256, 256>>>(hin, f2w, lng, lnb, outstep);
    }
}